// round 8
// baseline (speedup 1.0000x reference)
#include <cuda_runtime.h>
#include <cstdint>

#define BROWS 524288
#define HD 128
#define TM 64
#define NBLK (BROWS / TM)          // 8192
#define MAXIT 100
#define TOL2 1e-10
#define SMEMB 100352               // (128*132 + 64*128) * 4 bytes

__device__ float  g_ux[(size_t)BROWS * HD];
__device__ float  g_z0[(size_t)BROWS * HD];
__device__ float  g_z1[(size_t)BROWS * HD];
__device__ double g_part[NBLK];
__device__ int    g_state;   // 0 running, 1 converged, 3 maxiter-stop
__device__ int    g_iter;

// Shared GEMM tile: out_acc[8][4] = A_tile[64x128] @ Wg[128x128]^T
// wt = Wg transposed in smem, padded stride 132 (16B-aligned, conflict-free).
// zs = A tile [64][128]; reads are warp-broadcast (all lanes of a warp share ty).
#define GEMM_BODY(APTR, WPTR)                                              \
  extern __shared__ float sm[];                                            \
  float* wt = sm;                                                          \
  float* zs = sm + 16896;                                                  \
  int tid = threadIdx.x;                                                   \
  int tx = tid & 31, ty = tid >> 5;                                        \
  size_t row0 = (size_t)blockIdx.x * TM;                                   \
  for (int i = tid; i < 16384; i += 256) {                                 \
    int c = i >> 7, k = i & 127;                                           \
    wt[k * 132 + c] = (WPTR)[i];                                           \
  }                                                                        \
  {                                                                        \
    const float4* a4 = (const float4*)((APTR) + row0 * HD);                \
    float4* s4 = (float4*)zs;                                              \
    for (int i = tid; i < 2048; i += 256) s4[i] = a4[i];                   \
  }                                                                        \
  __syncthreads();                                                         \
  float acc[8][4];                                                         \
  _Pragma("unroll")                                                        \
  for (int i = 0; i < 8; i++)                                              \
    for (int j = 0; j < 4; j++) acc[i][j] = 0.f;                           \
  _Pragma("unroll 4")                                                      \
  for (int k = 0; k < 128; k++) {                                          \
    float4 b = *(const float4*)&wt[k * 132 + tx * 4];                      \
    _Pragma("unroll")                                                      \
    for (int i = 0; i < 8; i++) {                                          \
      float a = zs[(ty * 8 + i) * 128 + k];                                \
      acc[i][0] += a * b.x; acc[i][1] += a * b.y;                          \
      acc[i][2] += a * b.z; acc[i][3] += a * b.w;                          \
    }                                                                      \
  }

__global__ void k_init() { g_state = 0; g_iter = 0; }

// ux = x @ U_w^T + U_b; also zero z0 buffer.
__global__ void __launch_bounds__(256, 2) k_ux(const float* __restrict__ x,
                                               const float* __restrict__ Uw,
                                               const float* __restrict__ Ub) {
  GEMM_BODY(x, Uw)
  float4 ub = *(const float4*)&Ub[tx * 4];
  float4 zf = make_float4(0.f, 0.f, 0.f, 0.f);
#pragma unroll
  for (int i = 0; i < 8; i++) {
    int r = ty * 8 + i;
    size_t g = row0 * HD + r * HD + tx * 4;
    float4 o;
    o.x = acc[i][0] + ub.x; o.y = acc[i][1] + ub.y;
    o.z = acc[i][2] + ub.z; o.w = acc[i][3] + ub.w;
    *(float4*)&g_ux[g] = o;
    *(float4*)&g_z0[g] = zf;
  }
}

// One fixed-point iteration: z_next = tanh(z @ W^T + ux); block partial of ||diff||^2.
__global__ void __launch_bounds__(256, 2) k_step(const float* __restrict__ W, int par) {
  if (g_state) return;
  const float* zin = par ? g_z1 : g_z0;
  float* zout = par ? g_z0 : g_z1;
  GEMM_BODY(zin, W)
  double dsum = 0.0;
#pragma unroll
  for (int i = 0; i < 8; i++) {
    int r = ty * 8 + i;
    size_t g = row0 * HD + r * HD + tx * 4;
    float4 u = *(const float4*)&g_ux[g];
    float4 zo;
    zo.x = tanhf(acc[i][0] + u.x); zo.y = tanhf(acc[i][1] + u.y);
    zo.z = tanhf(acc[i][2] + u.z); zo.w = tanhf(acc[i][3] + u.w);
    float4 zp = *(const float4*)&zs[r * 128 + tx * 4];
    float dx = zo.x - zp.x, dy = zo.y - zp.y, dz = zo.z - zp.z, dw = zo.w - zp.w;
    dsum += (double)dx * dx + (double)dy * dy + (double)dz * dz + (double)dw * dw;
    *(float4*)&zout[g] = zo;
  }
  __shared__ double sred[256];
  sred[tid] = dsum;
  __syncthreads();
  for (int s = 128; s; s >>= 1) {
    if (tid < s) sred[tid] += sred[tid + s];
    __syncthreads();
  }
  if (tid == 0) g_part[blockIdx.x] = sred[0];
}

// Deterministic global reduction + state update.
__global__ void k_reduce() {
  if (g_state) return;
  __shared__ double s[1024];
  double v = 0.0;
  for (int i = threadIdx.x; i < NBLK; i += 1024) v += g_part[i];
  s[threadIdx.x] = v;
  __syncthreads();
  for (int st = 512; st; st >>= 1) {
    if (threadIdx.x < st) s[threadIdx.x] += s[threadIdx.x + st];
    __syncthreads();
  }
  if (threadIdx.x == 0) {
    g_iter++;
    if (s[0] < TOL2) g_state = 1;
    else if (g_iter >= MAXIT) g_state = 3;
  }
}

// Extra step (only if converged), writing straight to d_out.
__global__ void __launch_bounds__(256, 2) k_extra(const float* __restrict__ W,
                                                  float* __restrict__ out) {
  if (g_state != 1) return;
  const float* zin = (g_iter & 1) ? g_z1 : g_z0;
  GEMM_BODY(zin, W)
#pragma unroll
  for (int i = 0; i < 8; i++) {
    int r = ty * 8 + i;
    size_t g = row0 * HD + r * HD + tx * 4;
    float4 u = *(const float4*)&g_ux[g];
    float4 zo;
    zo.x = tanhf(acc[i][0] + u.x); zo.y = tanhf(acc[i][1] + u.y);
    zo.z = tanhf(acc[i][2] + u.z); zo.w = tanhf(acc[i][3] + u.w);
    *(float4*)&out[g] = zo;
  }
}

// Not-converged path: copy current z to d_out. Also append iterations/converged
// if the output buffer has room for them.
__global__ void k_final(float* __restrict__ out, long long osz) {
  if (g_state != 1) {
    const float* src = (g_iter & 1) ? g_z1 : g_z0;
    const float4* s4 = (const float4*)src;
    float4* o4 = (float4*)out;
    size_t idx = (size_t)blockIdx.x * blockDim.x + threadIdx.x;
    size_t stride = (size_t)gridDim.x * blockDim.x;
    for (size_t i = idx; i < 16777216; i += stride) o4[i] = s4[i];
  }
  if (blockIdx.x == 0 && threadIdx.x == 0) {
    long long n = (long long)BROWS * HD;
    if (osz >= n + 1) out[n] = (float)g_iter;
    if (osz >= n + 2) out[n + 1] = (g_state == 1) ? 1.0f : 0.0f;
  }
}

extern "C" void kernel_launch(void* const* d_in, const int* in_sizes, int n_in,
                              void* d_out, int out_size) {
  // Size-based remap (dict order: x, W, U_w, U_b).
  const float *x = 0, *W = 0, *Uw = 0, *Ub = 0;
  for (int i = 0; i < n_in; i++) {
    if (in_sizes[i] == BROWS * HD)      x  = (const float*)d_in[i];
    else if (in_sizes[i] == HD)         Ub = (const float*)d_in[i];
    else if (!W)                        W  = (const float*)d_in[i];
    else                                Uw = (const float*)d_in[i];
  }
  float* out = (float*)d_out;

  cudaFuncSetAttribute(k_ux,    cudaFuncAttributeMaxDynamicSharedMemorySize, SMEMB);
  cudaFuncSetAttribute(k_step,  cudaFuncAttributeMaxDynamicSharedMemorySize, SMEMB);
  cudaFuncSetAttribute(k_extra, cudaFuncAttributeMaxDynamicSharedMemorySize, SMEMB);

  k_init<<<1, 1>>>();
  k_ux<<<NBLK, 256, SMEMB>>>(x, Uw, Ub);
  for (int j = 0; j < MAXIT; j++) {
    k_step<<<NBLK, 256, SMEMB>>>(W, j & 1);
    k_reduce<<<1, 1024>>>();
  }
  k_extra<<<NBLK, 256, SMEMB>>>(W, out);
  k_final<<<NBLK, 256>>>(out, (long long)out_size);
}